// round 6
// baseline (speedup 1.0000x reference)
#include <cuda_runtime.h>

// Problem constants
#define B_   16
#define NQ_  512
#define NK_  1024
#define CQ_  128
#define H_   8
#define D_   64
#define HD_  512   // H_*D_

// Scratch for projected Q/K/V (device globals: no allocation in kernel_launch)
__device__ float g_Q[B_ * NQ_ * HD_];   // 16 MB
__device__ float g_K[B_ * NK_ * HD_];   // 32 MB
__device__ float g_V[B_ * NK_ * HD_];   // 32 MB

// ---------------------------------------------------------------------------
// Projection GEMM: Y[M,512] = X[M,128] @ W[128,512] + bias
// Block tile 128(M) x 64(N), K-chunks of 32, 256 threads, 8x4 micro-tile.
// ---------------------------------------------------------------------------
__global__ __launch_bounds__(256) void proj_gemm(
    const float* __restrict__ X, const float* __restrict__ W,
    const float* __restrict__ bias, float* __restrict__ Y)
{
    __shared__ float As[32 * 132];  // [k][m] transposed, stride 132 (pad)
    __shared__ float Bs[32 * 68];   // [k][n], stride 68 (pad)

    const int tid = threadIdx.x;
    const int tx = tid & 15;        // n groups of 4
    const int ty = tid >> 4;        // m groups of 8
    const int m0 = blockIdx.x * 128;
    const int n0 = blockIdx.y * 64;

    float acc[8][4];
#pragma unroll
    for (int i = 0; i < 8; i++)
#pragma unroll
        for (int j = 0; j < 4; j++) acc[i][j] = 0.f;

    for (int kc = 0; kc < 128; kc += 32) {
        __syncthreads();
        // X tile: 128 rows x 32 k  (1024 float4, 4 per thread), store transposed
#pragma unroll
        for (int r = 0; r < 4; r++) {
            int v = tid + r * 256;
            int row = v >> 3;
            int k4 = (v & 7) << 2;
            float4 x = *(const float4*)(X + (size_t)(m0 + row) * 128 + kc + k4);
            As[(k4 + 0) * 132 + row] = x.x;
            As[(k4 + 1) * 132 + row] = x.y;
            As[(k4 + 2) * 132 + row] = x.z;
            As[(k4 + 3) * 132 + row] = x.w;
        }
        // W tile: 32 rows x 64 n  (512 float4, 2 per thread)
#pragma unroll
        for (int r = 0; r < 2; r++) {
            int v = tid + r * 256;
            int wrow = v >> 4;
            int n4 = (v & 15) << 2;
            *(float4*)(&Bs[wrow * 68 + n4]) =
                *(const float4*)(W + (size_t)(kc + wrow) * 512 + n0 + n4);
        }
        __syncthreads();

#pragma unroll 8
        for (int kk = 0; kk < 32; kk++) {
            float4 a0 = *(const float4*)(&As[kk * 132 + ty * 8]);
            float4 a1 = *(const float4*)(&As[kk * 132 + ty * 8 + 4]);
            float4 b0 = *(const float4*)(&Bs[kk * 68 + tx * 4]);
            float av[8] = {a0.x, a0.y, a0.z, a0.w, a1.x, a1.y, a1.z, a1.w};
            float bv[4] = {b0.x, b0.y, b0.z, b0.w};
#pragma unroll
            for (int i = 0; i < 8; i++)
#pragma unroll
                for (int j = 0; j < 4; j++) acc[i][j] += av[i] * bv[j];
        }
    }

    float4 bz = *(const float4*)(bias + n0 + tx * 4);
#pragma unroll
    for (int i = 0; i < 8; i++) {
        float4 o;
        o.x = acc[i][0] + bz.x;
        o.y = acc[i][1] + bz.y;
        o.z = acc[i][2] + bz.z;
        o.w = acc[i][3] + bz.w;
        *(float4*)(Y + (size_t)(m0 + ty * 8 + i) * 512 + n0 + tx * 4) = o;
    }
}

// ---------------------------------------------------------------------------
// Fused flash-style attention.
// One block per (b, h, 128-query tile). 256 threads.
// Loop over NK in tiles of 64 keys: S = Qs@Kt, +mask, online softmax, O += P@V.
// Kt and Ps alias the same smem region (Kt consumed before Ps is written).
// ---------------------------------------------------------------------------
#define SQ 132   // stride for q-indexed rows (128 + pad)
#define SK 68    // stride for 64-wide rows (64 + pad)
#define ATTN_SMEM_BYTES ((128 * SQ + 64 * SK + 64) * 4)

__global__ __launch_bounds__(256, 2) void attn_kernel(
    const float* __restrict__ Q, const float* __restrict__ K,
    const float* __restrict__ V, const float* __restrict__ cmask,
    float* __restrict__ Out)
{
    extern __shared__ float sm[];
    float* Qt   = sm;                    // [64 d][128 q] stride SQ (pre-scaled)
    float* KtPs = sm + 64 * SQ;          // Kt: [64 d][64 k] stride SK; then Ps: [64 k][128 q] stride SQ
    float* Vs   = sm + 128 * SQ;         // [64 k][64 d] stride SK
    float* ma   = sm + 128 * SQ + 64 * SK;  // [64] additive mask

    const int tid = threadIdx.x;
    const int tx = tid & 15;   // GEMM1: k cols (x4) ; GEMM2: d cols (x4)
    const int ty = tid >> 4;   // q rows (x8)
    const int q0 = blockIdx.x * 128;
    const int h  = blockIdx.y;
    const int b  = blockIdx.z;

    const float* Qbase = Q + ((size_t)b * NQ_ + q0) * HD_ + h * D_;
    const float* Kbase = K + (size_t)b * NK_ * HD_ + h * D_;
    const float* Vbase = V + (size_t)b * NK_ * HD_ + h * D_;
    const float* Mbase = cmask + (size_t)b * NK_;

    // Load Q tile (128 q x 64 d), transposed, scaled by 1/sqrt(D)=0.125
#pragma unroll
    for (int r = 0; r < 8; r++) {
        int v = tid + r * 256;
        int row = v >> 4;
        int d4 = (v & 15) << 2;
        float4 x = *(const float4*)(Qbase + (size_t)row * HD_ + d4);
        Qt[(d4 + 0) * SQ + row] = x.x * 0.125f;
        Qt[(d4 + 1) * SQ + row] = x.y * 0.125f;
        Qt[(d4 + 2) * SQ + row] = x.z * 0.125f;
        Qt[(d4 + 3) * SQ + row] = x.w * 0.125f;
    }

    float m_i[8], l_i[8], acc[8][4];
#pragma unroll
    for (int i = 0; i < 8; i++) {
        m_i[i] = -1e30f;
        l_i[i] = 0.f;
#pragma unroll
        for (int j = 0; j < 4; j++) acc[i][j] = 0.f;
    }

    for (int k0 = 0; k0 < NK_; k0 += 64) {
        __syncthreads();  // prior GEMM2 done reading Ps/Vs; also covers Qt stores
        // Load K tile (transposed -> Kt[d][k]) and V tile (natural Vs[k][d])
#pragma unroll
        for (int r = 0; r < 4; r++) {
            int v = tid + r * 256;
            int row = v >> 4;
            int d4 = (v & 15) << 2;
            float4 x = *(const float4*)(Kbase + (size_t)(k0 + row) * HD_ + d4);
            KtPs[(d4 + 0) * SK + row] = x.x;
            KtPs[(d4 + 1) * SK + row] = x.y;
            KtPs[(d4 + 2) * SK + row] = x.z;
            KtPs[(d4 + 3) * SK + row] = x.w;
            float4 y = *(const float4*)(Vbase + (size_t)(k0 + row) * HD_ + d4);
            *(float4*)(&Vs[row * SK + d4]) = y;
        }
        if (tid < 64) ma[tid] = -100000.f * (1.f - Mbase[k0 + tid]);
        __syncthreads();

        // GEMM1: S[128q x 64k] = Qs @ K^T, thread tile 8q x 4k
        float s[8][4];
#pragma unroll
        for (int i = 0; i < 8; i++)
#pragma unroll
            for (int j = 0; j < 4; j++) s[i][j] = 0.f;
#pragma unroll 8
        for (int d = 0; d < 64; d++) {
            float4 a0 = *(const float4*)(&Qt[d * SQ + ty * 8]);
            float4 a1 = *(const float4*)(&Qt[d * SQ + ty * 8 + 4]);
            float4 kv = *(const float4*)(&KtPs[d * SK + tx * 4]);
            float av[8] = {a0.x, a0.y, a0.z, a0.w, a1.x, a1.y, a1.z, a1.w};
            float bv[4] = {kv.x, kv.y, kv.z, kv.w};
#pragma unroll
            for (int i = 0; i < 8; i++)
#pragma unroll
                for (int j = 0; j < 4; j++) s[i][j] += av[i] * bv[j];
        }

        // Additive mask
        float ma0 = ma[tx * 4 + 0], ma1 = ma[tx * 4 + 1];
        float ma2 = ma[tx * 4 + 2], ma3 = ma[tx * 4 + 3];
#pragma unroll
        for (int i = 0; i < 8; i++) {
            s[i][0] += ma0; s[i][1] += ma1; s[i][2] += ma2; s[i][3] += ma3;
        }

        // Online softmax. k dim is spread over the 16 tx lanes (lane bits 0-3),
        // so xor-shuffles 8,4,2,1 reduce within each tx-group.
#pragma unroll
        for (int i = 0; i < 8; i++) {
            float rm = fmaxf(fmaxf(s[i][0], s[i][1]), fmaxf(s[i][2], s[i][3]));
#pragma unroll
            for (int off = 8; off > 0; off >>= 1)
                rm = fmaxf(rm, __shfl_xor_sync(0xffffffffu, rm, off));
            float nm = fmaxf(m_i[i], rm);
            float corr = __expf(m_i[i] - nm);
            m_i[i] = nm;
            float rs = 0.f;
#pragma unroll
            for (int j = 0; j < 4; j++) {
                s[i][j] = __expf(s[i][j] - nm);
                rs += s[i][j];
            }
#pragma unroll
            for (int off = 8; off > 0; off >>= 1)
                rs += __shfl_xor_sync(0xffffffffu, rs, off);
            l_i[i] = l_i[i] * corr + rs;
#pragma unroll
            for (int j = 0; j < 4; j++) acc[i][j] *= corr;
        }

        __syncthreads();  // all Kt reads done before Ps overwrites the region
        // Write P transposed: Ps[k][q]
#pragma unroll
        for (int j = 0; j < 4; j++)
#pragma unroll
            for (int i = 0; i < 8; i++)
                KtPs[(tx * 4 + j) * SQ + ty * 8 + i] = s[i][j];
        __syncthreads();

        // GEMM2: O[128q x 64d] += P @ V, thread tile 8q x 4d
#pragma unroll 8
        for (int k = 0; k < 64; k++) {
            float4 p0 = *(const float4*)(&KtPs[k * SQ + ty * 8]);
            float4 p1 = *(const float4*)(&KtPs[k * SQ + ty * 8 + 4]);
            float4 vv = *(const float4*)(&Vs[k * SK + tx * 4]);
            float pv[8] = {p0.x, p0.y, p0.z, p0.w, p1.x, p1.y, p1.z, p1.w};
            float vvv[4] = {vv.x, vv.y, vv.z, vv.w};
#pragma unroll
            for (int i = 0; i < 8; i++)
#pragma unroll
                for (int j = 0; j < 4; j++) acc[i][j] += pv[i] * vvv[j];
        }
    }

    // Epilogue: divide by softmax denominator and store
    float* Obase = Out + ((size_t)b * NQ_ + q0) * HD_ + h * D_;
#pragma unroll
    for (int i = 0; i < 8; i++) {
        float inv = 1.f / l_i[i];
        float4 o;
        o.x = acc[i][0] * inv;
        o.y = acc[i][1] * inv;
        o.z = acc[i][2] * inv;
        o.w = acc[i][3] * inv;
        *(float4*)(Obase + (size_t)(ty * 8 + i) * HD_ + tx * 4) = o;
    }
}

// ---------------------------------------------------------------------------
// Launch: 3 projection GEMMs -> fused attention. Graph-capturable: kernel
// launches only (cudaGetSymbolAddress / cudaFuncSetAttribute are immediate,
// non-stream, allocation-free APIs).
// ---------------------------------------------------------------------------
extern "C" void kernel_launch(void* const* d_in, const int* in_sizes, int n_in,
                              void* d_out, int out_size)
{
    (void)in_sizes; (void)n_in; (void)out_size;
    const float* query = (const float*)d_in[0];  // [16,512,128]
    const float* key   = (const float*)d_in[1];  // [16,1024,128]
    const float* cmask = (const float*)d_in[2];  // [16,1024]
    const float* Wq    = (const float*)d_in[3];  // [128,512]
    const float* bq    = (const float*)d_in[4];
    const float* Wk    = (const float*)d_in[5];
    const float* bk    = (const float*)d_in[6];
    const float* Wv    = (const float*)d_in[7];
    const float* bv    = (const float*)d_in[8];
    float* out = (float*)d_out;                  // [16,512,512]

    float *qbuf, *kbuf, *vbuf;
    cudaGetSymbolAddress((void**)&qbuf, g_Q);
    cudaGetSymbolAddress((void**)&kbuf, g_K);
    cudaGetSymbolAddress((void**)&vbuf, g_V);

    dim3 blk(256);
    // Q: M = 16*512 = 8192 -> 64 M-tiles; K/V: M = 16*1024 = 16384 -> 128 M-tiles
    proj_gemm<<<dim3(64, 8), blk>>>(query, Wq, bq, qbuf);
    proj_gemm<<<dim3(128, 8), blk>>>(key, Wk, bk, kbuf);
    proj_gemm<<<dim3(128, 8), blk>>>(key, Wv, bv, vbuf);

    cudaFuncSetAttribute(attn_kernel,
                         cudaFuncAttributeMaxDynamicSharedMemorySize,
                         ATTN_SMEM_BYTES);
    // grid: (NQ/128, H, B) = (4, 8, 16) = 512 blocks
    attn_kernel<<<dim3(NQ_ / 128, H_, B_), blk, ATTN_SMEM_BYTES>>>(
        qbuf, kbuf, vbuf, cmask, out);
}

// round 11
// speedup vs baseline: 1.0663x; 1.0663x over previous
#include <cuda_runtime.h>
#include <cstdint>

// Problem constants
#define B_   16
#define NQ_  512
#define NK_  1024
#define CQ_  128
#define H_   8
#define D_   64
#define HD_  512   // H_*D_

// Scratch for projected Q/K/V (device globals: no allocation in kernel_launch)
__device__ float g_Q[B_ * NQ_ * HD_];   // 16 MB
__device__ float g_K[B_ * NK_ * HD_];   // 32 MB
__device__ float g_V[B_ * NK_ * HD_];   // 32 MB

// ---------------------------------------------------------------------------
// Packed f32x2 helpers (sm_103a): one instruction = 2 fp32 lanes.
// FFMA-3reg issues at rt=2/SMSP; fma.rn.f32x2 doubles math per issue slot.
// ---------------------------------------------------------------------------
__device__ __forceinline__ uint64_t dup2(float x) {
    uint64_t r; uint32_t u = __float_as_uint(x);
    asm("mov.b64 %0, {%1, %1};" : "=l"(r) : "r"(u));
    return r;
}
__device__ __forceinline__ uint64_t pack2(float lo, float hi) {
    uint64_t r; uint32_t a = __float_as_uint(lo), b = __float_as_uint(hi);
    asm("mov.b64 %0, {%1, %2};" : "=l"(r) : "r"(a), "r"(b));
    return r;
}
__device__ __forceinline__ void unpack2(uint64_t v, float& lo, float& hi) {
    uint32_t a, b;
    asm("mov.b64 {%0, %1}, %2;" : "=r"(a), "=r"(b) : "l"(v));
    lo = __uint_as_float(a); hi = __uint_as_float(b);
}
__device__ __forceinline__ uint64_t ffma2(uint64_t a, uint64_t b, uint64_t c) {
    uint64_t d;
    asm("fma.rn.f32x2 %0, %1, %2, %3;" : "=l"(d) : "l"(a), "l"(b), "l"(c));
    return d;
}
__device__ __forceinline__ uint64_t fmul2(uint64_t a, uint64_t b) {
    uint64_t d;
    asm("mul.rn.f32x2 %0, %1, %2;" : "=l"(d) : "l"(a), "l"(b));
    return d;
}

// ---------------------------------------------------------------------------
// Projection GEMM: Y[M,512] = X[M,128] @ W[128,512] + bias
// Block tile 128(M) x 64(N), K-chunks of 32, 256 threads, 8x4 micro-tile.
// Accumulators packed over m-row pairs (f32x2).
// ---------------------------------------------------------------------------
__global__ __launch_bounds__(256) void proj_gemm(
    const float* __restrict__ X, const float* __restrict__ W,
    const float* __restrict__ bias, float* __restrict__ Y)
{
    __shared__ float As[32 * 132];  // [k][m] transposed, stride 132 (pad)
    __shared__ float Bs[32 * 68];   // [k][n], stride 68 (pad)

    const int tid = threadIdx.x;
    const int tx = tid & 15;        // n groups of 4
    const int ty = tid >> 4;        // m groups of 8
    const int m0 = blockIdx.x * 128;
    const int n0 = blockIdx.y * 64;

    uint64_t acc2[4][4];            // [m-pair][n]
#pragma unroll
    for (int ip = 0; ip < 4; ip++)
#pragma unroll
        for (int j = 0; j < 4; j++) acc2[ip][j] = 0ull;

    for (int kc = 0; kc < 128; kc += 32) {
        __syncthreads();
        // X tile: 128 rows x 32 k (1024 float4, 4/thread), store transposed
#pragma unroll
        for (int r = 0; r < 4; r++) {
            int v = tid + r * 256;
            int row = v >> 3;
            int k4 = (v & 7) << 2;
            float4 x = *(const float4*)(X + (size_t)(m0 + row) * 128 + kc + k4);
            As[(k4 + 0) * 132 + row] = x.x;
            As[(k4 + 1) * 132 + row] = x.y;
            As[(k4 + 2) * 132 + row] = x.z;
            As[(k4 + 3) * 132 + row] = x.w;
        }
        // W tile: 32 rows x 64 n (512 float4, 2/thread)
#pragma unroll
        for (int r = 0; r < 2; r++) {
            int v = tid + r * 256;
            int wrow = v >> 4;
            int n4 = (v & 15) << 2;
            *(float4*)(&Bs[wrow * 68 + n4]) =
                *(const float4*)(W + (size_t)(kc + wrow) * 512 + n0 + n4);
        }
        __syncthreads();

#pragma unroll 8
        for (int kk = 0; kk < 32; kk++) {
            const ulonglong2* ap =
                (const ulonglong2*)(&As[kk * 132 + ty * 8]);
            ulonglong2 A0 = ap[0], A1 = ap[1];
            uint64_t a2[4] = {A0.x, A0.y, A1.x, A1.y};
            float4 b0 = *(const float4*)(&Bs[kk * 68 + tx * 4]);
            uint64_t bd[4] = {dup2(b0.x), dup2(b0.y), dup2(b0.z), dup2(b0.w)};
#pragma unroll
            for (int ip = 0; ip < 4; ip++)
#pragma unroll
                for (int j = 0; j < 4; j++)
                    acc2[ip][j] = ffma2(a2[ip], bd[j], acc2[ip][j]);
        }
    }

    float4 bz = *(const float4*)(bias + n0 + tx * 4);
#pragma unroll
    for (int ip = 0; ip < 4; ip++) {
        float lo[4], hi[4];
#pragma unroll
        for (int j = 0; j < 4; j++) unpack2(acc2[ip][j], lo[j], hi[j]);
        float4 o0 = make_float4(lo[0] + bz.x, lo[1] + bz.y,
                                lo[2] + bz.z, lo[3] + bz.w);
        float4 o1 = make_float4(hi[0] + bz.x, hi[1] + bz.y,
                                hi[2] + bz.z, hi[3] + bz.w);
        *(float4*)(Y + (size_t)(m0 + ty * 8 + 2 * ip) * 512 + n0 + tx * 4) = o0;
        *(float4*)(Y + (size_t)(m0 + ty * 8 + 2 * ip + 1) * 512 + n0 + tx * 4) = o1;
    }
}

// ---------------------------------------------------------------------------
// Fused flash-style attention (fp32, f32x2-packed GEMMs).
// One block per (b, h, 128-query tile). 256 threads.
// Loop over NK in tiles of 64 keys: S = Qs@Kt, +mask, online softmax, O += P@V.
// Kt and Ps alias the same smem region (Kt consumed before Ps is written).
// ---------------------------------------------------------------------------
#define SQ 132   // stride for q-indexed rows (128 + pad)
#define SK 68    // stride for 64-wide rows (64 + pad)
#define ATTN_SMEM_BYTES ((128 * SQ + 64 * SK + 64) * 4)

__global__ __launch_bounds__(256, 2) void attn_kernel(
    const float* __restrict__ Q, const float* __restrict__ K,
    const float* __restrict__ V, const float* __restrict__ cmask,
    float* __restrict__ Out)
{
    extern __shared__ float sm[];
    float* Qt   = sm;                    // [64 d][128 q] stride SQ (pre-scaled)
    float* KtPs = sm + 64 * SQ;          // Kt: [64 d][64 k] SK; then Ps: [64 k][128 q] SQ
    float* Vs   = sm + 128 * SQ;         // [64 k][64 d] stride SK
    float* ma   = sm + 128 * SQ + 64 * SK;  // [64] additive mask

    const int tid = threadIdx.x;
    const int tx = tid & 15;   // GEMM1: k cols (x4) ; GEMM2: d cols (x4)
    const int ty = tid >> 4;   // q rows (x8)
    const int q0 = blockIdx.x * 128;
    const int h  = blockIdx.y;
    const int b  = blockIdx.z;

    const float* Qbase = Q + ((size_t)b * NQ_ + q0) * HD_ + h * D_;
    const float* Kbase = K + (size_t)b * NK_ * HD_ + h * D_;
    const float* Vbase = V + (size_t)b * NK_ * HD_ + h * D_;
    const float* Mbase = cmask + (size_t)b * NK_;

    // Load Q tile (128 q x 64 d), transposed, scaled by 1/sqrt(D)=0.125
#pragma unroll
    for (int r = 0; r < 8; r++) {
        int v = tid + r * 256;
        int row = v >> 4;
        int d4 = (v & 15) << 2;
        float4 x = *(const float4*)(Qbase + (size_t)row * HD_ + d4);
        Qt[(d4 + 0) * SQ + row] = x.x * 0.125f;
        Qt[(d4 + 1) * SQ + row] = x.y * 0.125f;
        Qt[(d4 + 2) * SQ + row] = x.z * 0.125f;
        Qt[(d4 + 3) * SQ + row] = x.w * 0.125f;
    }

    float m_i[8], l_i[8];
    uint64_t o2[4][4];   // [q-pair][d]
#pragma unroll
    for (int i = 0; i < 8; i++) { m_i[i] = -1e30f; l_i[i] = 0.f; }
#pragma unroll
    for (int ip = 0; ip < 4; ip++)
#pragma unroll
        for (int j = 0; j < 4; j++) o2[ip][j] = 0ull;

    for (int k0 = 0; k0 < NK_; k0 += 64) {
        __syncthreads();  // prior GEMM2 done reading Ps/Vs; also covers Qt stores
        // Load K tile (transposed -> Kt[d][k]) and V tile (natural Vs[k][d])
#pragma unroll
        for (int r = 0; r < 4; r++) {
            int v = tid + r * 256;
            int row = v >> 4;
            int d4 = (v & 15) << 2;
            float4 x = *(const float4*)(Kbase + (size_t)(k0 + row) * HD_ + d4);
            KtPs[(d4 + 0) * SK + row] = x.x;
            KtPs[(d4 + 1) * SK + row] = x.y;
            KtPs[(d4 + 2) * SK + row] = x.z;
            KtPs[(d4 + 3) * SK + row] = x.w;
            float4 y = *(const float4*)(Vbase + (size_t)(k0 + row) * HD_ + d4);
            *(float4*)(&Vs[row * SK + d4]) = y;
        }
        if (tid < 64) ma[tid] = -100000.f * (1.f - Mbase[k0 + tid]);
        __syncthreads();

        // GEMM1: S[128q x 64k] = Qs @ K^T, packed over q-row pairs
        uint64_t s2[4][4];
#pragma unroll
        for (int ip = 0; ip < 4; ip++)
#pragma unroll
            for (int j = 0; j < 4; j++) s2[ip][j] = 0ull;
#pragma unroll 8
        for (int d = 0; d < 64; d++) {
            const ulonglong2* ap =
                (const ulonglong2*)(&Qt[d * SQ + ty * 8]);
            ulonglong2 A0 = ap[0], A1 = ap[1];
            uint64_t a2[4] = {A0.x, A0.y, A1.x, A1.y};
            float4 kv = *(const float4*)(&KtPs[d * SK + tx * 4]);
            uint64_t bd[4] = {dup2(kv.x), dup2(kv.y), dup2(kv.z), dup2(kv.w)};
#pragma unroll
            for (int ip = 0; ip < 4; ip++)
#pragma unroll
                for (int j = 0; j < 4; j++)
                    s2[ip][j] = ffma2(a2[ip], bd[j], s2[ip][j]);
        }

        // Unpack scores to scalar [8][4]
        float s[8][4];
#pragma unroll
        for (int ip = 0; ip < 4; ip++)
#pragma unroll
            for (int j = 0; j < 4; j++)
                unpack2(s2[ip][j], s[2 * ip][j], s[2 * ip + 1][j]);

        // Additive mask
        float ma0 = ma[tx * 4 + 0], ma1 = ma[tx * 4 + 1];
        float ma2v = ma[tx * 4 + 2], ma3 = ma[tx * 4 + 3];
#pragma unroll
        for (int i = 0; i < 8; i++) {
            s[i][0] += ma0; s[i][1] += ma1; s[i][2] += ma2v; s[i][3] += ma3;
        }

        // Online softmax. k spread over the 16 tx lanes (lane bits 0-3):
        // xor-shuffles 8,4,2,1 reduce within each tx-group.
        float corr[8];
#pragma unroll
        for (int i = 0; i < 8; i++) {
            float rm = fmaxf(fmaxf(s[i][0], s[i][1]), fmaxf(s[i][2], s[i][3]));
#pragma unroll
            for (int off = 8; off > 0; off >>= 1)
                rm = fmaxf(rm, __shfl_xor_sync(0xffffffffu, rm, off));
            float nm = fmaxf(m_i[i], rm);
            corr[i] = __expf(m_i[i] - nm);
            m_i[i] = nm;
            float rs = 0.f;
#pragma unroll
            for (int j = 0; j < 4; j++) {
                s[i][j] = __expf(s[i][j] - nm);
                rs += s[i][j];
            }
#pragma unroll
            for (int off = 8; off > 0; off >>= 1)
                rs += __shfl_xor_sync(0xffffffffu, rs, off);
            l_i[i] = l_i[i] * corr[i] + rs;
        }
        // Packed rescale of O accumulators
#pragma unroll
        for (int ip = 0; ip < 4; ip++) {
            uint64_t c2 = pack2(corr[2 * ip], corr[2 * ip + 1]);
#pragma unroll
            for (int j = 0; j < 4; j++) o2[ip][j] = fmul2(o2[ip][j], c2);
        }

        __syncthreads();  // all Kt reads done before Ps overwrites the region
        // Write P transposed: Ps[k][q]
#pragma unroll
        for (int j = 0; j < 4; j++)
#pragma unroll
            for (int i = 0; i < 8; i++)
                KtPs[(tx * 4 + j) * SQ + ty * 8 + i] = s[i][j];
        __syncthreads();

        // GEMM2: O[128q x 64d] += P @ V, packed over q-row pairs
#pragma unroll 8
        for (int k = 0; k < 64; k++) {
            const ulonglong2* pp =
                (const ulonglong2*)(&KtPs[k * SQ + ty * 8]);
            ulonglong2 P0 = pp[0], P1 = pp[1];
            uint64_t a2[4] = {P0.x, P0.y, P1.x, P1.y};
            float4 vv = *(const float4*)(&Vs[k * SK + tx * 4]);
            uint64_t bd[4] = {dup2(vv.x), dup2(vv.y), dup2(vv.z), dup2(vv.w)};
#pragma unroll
            for (int ip = 0; ip < 4; ip++)
#pragma unroll
                for (int j = 0; j < 4; j++)
                    o2[ip][j] = ffma2(a2[ip], bd[j], o2[ip][j]);
        }
    }

    // Epilogue: divide by softmax denominator and store
    float* Obase = Out + ((size_t)b * NQ_ + q0) * HD_ + h * D_;
#pragma unroll
    for (int ip = 0; ip < 4; ip++) {
        float lo[4], hi[4];
#pragma unroll
        for (int j = 0; j < 4; j++) unpack2(o2[ip][j], lo[j], hi[j]);
        float inv0 = 1.f / l_i[2 * ip];
        float inv1 = 1.f / l_i[2 * ip + 1];
        float4 r0 = make_float4(lo[0] * inv0, lo[1] * inv0,
                                lo[2] * inv0, lo[3] * inv0);
        float4 r1 = make_float4(hi[0] * inv1, hi[1] * inv1,
                                hi[2] * inv1, hi[3] * inv1);
        *(float4*)(Obase + (size_t)(ty * 8 + 2 * ip) * HD_ + tx * 4) = r0;
        *(float4*)(Obase + (size_t)(ty * 8 + 2 * ip + 1) * HD_ + tx * 4) = r1;
    }
}

// ---------------------------------------------------------------------------
// Launch: 3 projection GEMMs -> fused attention. Graph-capturable.
// ---------------------------------------------------------------------------
extern "C" void kernel_launch(void* const* d_in, const int* in_sizes, int n_in,
                              void* d_out, int out_size)
{
    (void)in_sizes; (void)n_in; (void)out_size;
    const float* query = (const float*)d_in[0];  // [16,512,128]
    const float* key   = (const float*)d_in[1];  // [16,1024,128]
    const float* cmask = (const float*)d_in[2];  // [16,1024]
    const float* Wq    = (const float*)d_in[3];  // [128,512]
    const float* bq    = (const float*)d_in[4];
    const float* Wk    = (const float*)d_in[5];
    const float* bk    = (const float*)d_in[6];
    const float* Wv    = (const float*)d_in[7];
    const float* bv    = (const float*)d_in[8];
    float* out = (float*)d_out;                  // [16,512,512]

    float *qbuf, *kbuf, *vbuf;
    cudaGetSymbolAddress((void**)&qbuf, g_Q);
    cudaGetSymbolAddress((void**)&kbuf, g_K);
    cudaGetSymbolAddress((void**)&vbuf, g_V);

    dim3 blk(256);
    // Q: M = 16*512 = 8192 -> 64 M-tiles; K/V: M = 16*1024 = 16384 -> 128
    proj_gemm<<<dim3(64, 8), blk>>>(query, Wq, bq, qbuf);
    proj_gemm<<<dim3(128, 8), blk>>>(key, Wk, bk, kbuf);
    proj_gemm<<<dim3(128, 8), blk>>>(key, Wv, bv, vbuf);

    cudaFuncSetAttribute(attn_kernel,
                         cudaFuncAttributeMaxDynamicSharedMemorySize,
                         ATTN_SMEM_BYTES);
    // grid: (NQ/128, H, B) = (4, 8, 16) = 512 blocks
    attn_kernel<<<dim3(NQ_ / 128, H_, B_), blk, ATTN_SMEM_BYTES>>>(
        qbuf, kbuf, vbuf, cmask, out);
}